// round 14
// baseline (speedup 1.0000x reference)
#include <cuda_runtime.h>
#include <cuda_bf16.h>
#include <cuda_fp16.h>
#include <math.h>
#include <stdint.h>

// Problem constants
#define BB 2
#define TT 2048
#define CC 1024
#define NH 16
#define HD 64
#define HID 2816
#define BT (BB*TT)          // 4096 rows

// ===========================================================================
// Scratch (static device globals; no allocations anywhere)
// ===========================================================================
__device__ __align__(16) __half g_h16[BT*CC];        // rmsnorm out (fp16)
__device__ __align__(16) float  g_qkv[BT*3*CC];
__device__ __align__(16) __half g_qh [BB*NH*TT*HD];  // roped q hi (fp16)
__device__ __align__(16) __half g_ql [BB*NH*TT*HD];  // roped q lo
__device__ __align__(16) __half g_k16[BB*NH*TT*HD];  // roped k (single fp16)
__device__ __align__(16) __half g_vth[BB*NH*HD*TT];  // [bh][d][t] hi
__device__ __align__(16) __half g_vtl[BB*NH*HD*TT];  // [bh][d][t] lo
__device__ __align__(16) __half g_y16[BT*CC];        // attn out (fp16)
__device__ __align__(16) float  g_x1 [BT*CC];
__device__ __align__(16) float  g_fc1[BT*HID];
__device__ __align__(16) float  g_fc2[BT*HID];
__device__ __align__(16) __half g_a16[BT*HID];       // silu out (fp16)
// transposed + split weights, [N,K] K-major fp16 hi/lo
__device__ __align__(16) __half g_wqkv_h[3*CC*CC];
__device__ __align__(16) __half g_wqkv_l[3*CC*CC];
__device__ __align__(16) __half g_watt_h[CC*CC];
__device__ __align__(16) __half g_watt_l[CC*CC];
__device__ __align__(16) __half g_wf1_h[HID*CC];
__device__ __align__(16) __half g_wf1_l[HID*CC];
__device__ __align__(16) __half g_wf2_h[HID*CC];
__device__ __align__(16) __half g_wf2_l[HID*CC];
__device__ __align__(16) __half g_wmlp_h[CC*HID];
__device__ __align__(16) __half g_wmlp_l[CC*HID];

__device__ __forceinline__ void split_store_h(float v, __half* ph, __half* pl) {
    __half hi = __float2half(v);
    *ph = hi;
    *pl = __float2half(v - __half2float(hi));
}

__device__ __forceinline__ uint32_t smem_to_u32(const void* p) {
    uint32_t a;
    asm("{ .reg .u64 t; cvta.to.shared.u64 t, %1; cvt.u32.u64 %0, t; }" : "=r"(a) : "l"(p));
    return a;
}

// ===========================================================================
// mma.sync / ldmatrix / cp.async helpers (all valid on compute_103)
// ===========================================================================
__device__ __forceinline__ void ldsm_x4(uint32_t& r0, uint32_t& r1, uint32_t& r2,
                                        uint32_t& r3, uint32_t addr) {
    asm volatile("ldmatrix.sync.aligned.m8n8.x4.shared.b16 {%0,%1,%2,%3}, [%4];"
                 : "=r"(r0), "=r"(r1), "=r"(r2), "=r"(r3) : "r"(addr));
}
__device__ __forceinline__ void mma_fp16(float* d, const uint32_t* a, const uint32_t* b) {
    asm volatile(
        "mma.sync.aligned.m16n8k16.row.col.f32.f16.f16.f32 "
        "{%0,%1,%2,%3}, {%4,%5,%6,%7}, {%8,%9}, {%0,%1,%2,%3};"
        : "+f"(d[0]), "+f"(d[1]), "+f"(d[2]), "+f"(d[3])
        : "r"(a[0]), "r"(a[1]), "r"(a[2]), "r"(a[3]), "r"(b[0]), "r"(b[1]));
}
#define CP_ASYNC16(dst, src) \
    asm volatile("cp.async.cg.shared.global [%0], [%1], 16;" :: "r"(dst), "l"(src))
#define CP_COMMIT() asm volatile("cp.async.commit_group;" ::: "memory")
#define CP_WAIT(n)  asm volatile("cp.async.wait_group %0;" :: "n"(n) : "memory")

__device__ __forceinline__ uint32_t pack_h2(float f0, float f1) {
    __half2 h = __floats2half2_rn(f0, f1);
    return *reinterpret_cast<uint32_t*>(&h);
}

// ===========================================================================
// Merged weight transpose + fp16 split: all 5 weights in one launch.
// ===========================================================================
struct TpAll {
    const float* W[5];
    __half* Th[5];
    __half* Tl[5];
    int K[5];
    int N[5];
    int start[6];
};

__global__ __launch_bounds__(256) void tpose_all_kernel(TpAll p)
{
    __shared__ float tile[32][33];
    int bid = blockIdx.x;
    int w = 0;
    #pragma unroll
    for (int i = 0; i < 4; ++i) if (bid >= p.start[i + 1]) w = i + 1;
    const int local = bid - p.start[w];
    const int K = p.K[w], N = p.N[w];
    const int ntn = N >> 5;
    const int n0 = (local % ntn) * 32, k0 = (local / ntn) * 32;
    const float* W = p.W[w];
    __half* Th = p.Th[w];
    __half* Tl = p.Tl[w];

    const int tx = threadIdx.x & 31, ty = threadIdx.x >> 5;
    #pragma unroll
    for (int i = 0; i < 4; ++i) {
        int k = ty + i * 8;
        tile[k][tx] = W[(size_t)(k0 + k) * N + n0 + tx];
    }
    __syncthreads();
    #pragma unroll
    for (int i = 0; i < 4; ++i) {
        int n = ty + i * 8;
        float v = tile[tx][n];
        size_t idx = (size_t)(n0 + n) * K + k0 + tx;
        split_store_h(v, &Th[idx], &Tl[idx]);
    }
}

// ===========================================================================
// RMSNorm -> single fp16 output
// ===========================================================================
__global__ __launch_bounds__(256) void rmsnorm_h_kernel(
    const float* __restrict__ x, const float* __restrict__ scale,
    __half* __restrict__ oh)
{
    const int row = blockIdx.x;
    const int t   = threadIdx.x;
    float4 v = reinterpret_cast<const float4*>(x + (size_t)row * CC)[t];
    float ss = v.x*v.x + v.y*v.y + v.z*v.z + v.w*v.w;
    __shared__ float red[8];
    #pragma unroll
    for (int o = 16; o > 0; o >>= 1) ss += __shfl_down_sync(0xffffffffu, ss, o);
    if ((t & 31) == 0) red[t >> 5] = ss;
    __syncthreads();
    if (t < 32) {
        float s2 = (t < 8) ? red[t] : 0.f;
        #pragma unroll
        for (int o = 4; o > 0; o >>= 1) s2 += __shfl_down_sync(0xffffffffu, s2, o);
        if (t == 0) red[0] = s2;
    }
    __syncthreads();
    const float rs = rsqrtf(red[0] * (1.0f / CC) + 1e-5f);
    const float4 s4 = reinterpret_cast<const float4*>(scale)[t];
    __half2 o01 = __floats2half2_rn(v.x * rs * s4.x, v.y * rs * s4.y);
    __half2 o23 = __floats2half2_rn(v.z * rs * s4.z, v.w * rs * s4.w);
    uint2 pack;
    pack.x = *reinterpret_cast<uint32_t*>(&o01);
    pack.y = *reinterpret_cast<uint32_t*>(&o23);
    reinterpret_cast<uint2*>(oh + (size_t)row * CC)[t] = pack;
}

// ===========================================================================
// HMMA GEMM (fp16, 2-combo): C[M,N] = A[M,K] @ (Bh+Bl)[N,K]^T (+ R)
// CTA 128x128, BK=32, 8 warps (2x4), warp tile 64x32, m16n8k16 f16.
// ===========================================================================
#define TROW 80                       // padded row stride (bytes)
#define TILE_B (128*TROW)             // 10240 B per matrix tile
#define STAGE_B (3*TILE_B)            // A,Bh,Bl = 30720 B
#define GSM_TOTAL (2*STAGE_B)         // 61440 B

__global__ __launch_bounds__(256) void gemm_kernel(
    int M, int N, int K,
    const __half* __restrict__ A,
    const __half* __restrict__ Bh, const __half* __restrict__ Bl,
    const float* __restrict__ R, float* __restrict__ C)
{
    extern __shared__ char sm[];
    const uint32_t smb = smem_to_u32(sm);
    const int tid = threadIdx.x;
    const int wid = tid >> 5, lane = tid & 31;
    const int warp_m = wid >> 2;          // 0..1
    const int warp_n = wid & 3;           // 0..3
    const int m0 = blockIdx.y * 128, n0 = blockIdx.x * 128;

    const __half* srcs[3] = {
        A + (size_t)m0 * K, Bh + (size_t)n0 * K, Bl + (size_t)n0 * K };

    const int NC = K >> 5;   // chunks of 32

    auto load_stage = [&](int stage, int kc) {
        const uint32_t sb = smb + stage * STAGE_B;
        #pragma unroll
        for (int mtx = 0; mtx < 3; ++mtx) {
            const __half* s = srcs[mtx] + kc;
            const uint32_t tb = sb + mtx * TILE_B;
            #pragma unroll
            for (int u = tid; u < 512; u += 256) {
                const int row = u >> 2, q = u & 3;
                CP_ASYNC16(tb + row * TROW + q * 16, s + (size_t)row * K + q * 8);
            }
        }
        CP_COMMIT();
    };

    load_stage(0, 0);
    if (NC > 1) load_stage(1, 32);

    float acc[4][4][4] = {};

    const uint32_t aoff = (uint32_t)((lane & 15) * TROW + (lane >> 4) * 16);
    const uint32_t boff = (uint32_t)(((lane & 7) + ((lane >> 4) << 3)) * TROW
                                     + (((lane >> 3) & 1) << 4));

    for (int c = 0; c < NC; ++c) {
        if (c + 1 < NC) { CP_WAIT(1); } else { CP_WAIT(0); }
        __syncthreads();

        const uint32_t sb = smb + (c & 1) * STAGE_B;
        const uint32_t baseA  = sb              + (uint32_t)(warp_m * 64) * TROW;
        const uint32_t baseBh = sb + TILE_B     + (uint32_t)(warp_n * 32) * TROW;
        const uint32_t baseBl = sb + 2 * TILE_B + (uint32_t)(warp_n * 32) * TROW;

        #pragma unroll
        for (int kk = 0; kk < 2; ++kk) {
            const uint32_t kb = kk * 32;
            uint32_t bh[4][2], bl[4][2];
            #pragma unroll
            for (int pr = 0; pr < 2; ++pr) {
                uint32_t r0, r1, r2, r3;
                ldsm_x4(r0, r1, r2, r3, baseBh + (uint32_t)(pr * 16) * TROW + kb + boff);
                bh[2*pr][0] = r0; bh[2*pr][1] = r1; bh[2*pr+1][0] = r2; bh[2*pr+1][1] = r3;
                ldsm_x4(r0, r1, r2, r3, baseBl + (uint32_t)(pr * 16) * TROW + kb + boff);
                bl[2*pr][0] = r0; bl[2*pr][1] = r1; bl[2*pr+1][0] = r2; bl[2*pr+1][1] = r3;
            }
            uint32_t af[4][4];
            #pragma unroll
            for (int mt = 0; mt < 4; ++mt)
                ldsm_x4(af[mt][0], af[mt][1], af[mt][2], af[mt][3],
                        baseA + (uint32_t)(mt * 16) * TROW + kb + aoff);
            #pragma unroll
            for (int mt = 0; mt < 4; ++mt)
                #pragma unroll
                for (int nt = 0; nt < 4; ++nt)
                    mma_fp16(acc[mt][nt], af[mt], bh[nt]);
            #pragma unroll
            for (int mt = 0; mt < 4; ++mt)
                #pragma unroll
                for (int nt = 0; nt < 4; ++nt)
                    mma_fp16(acc[mt][nt], af[mt], bl[nt]);
        }
        __syncthreads();
        if (c + 2 < NC) load_stage(c & 1, (c + 2) << 5);
    }

    const int rl = lane >> 2, cl = (lane & 3) * 2;
    #pragma unroll
    for (int mt = 0; mt < 4; ++mt) {
        #pragma unroll
        for (int nt = 0; nt < 4; ++nt) {
            const int row = m0 + warp_m * 64 + mt * 16 + rl;
            const int col = n0 + warp_n * 32 + nt * 8 + cl;
            float2 v0 = make_float2(acc[mt][nt][0], acc[mt][nt][1]);
            float2 v1 = make_float2(acc[mt][nt][2], acc[mt][nt][3]);
            if (R) {
                float2 r0 = *reinterpret_cast<const float2*>(&R[(size_t)row * N + col]);
                float2 r1 = *reinterpret_cast<const float2*>(&R[(size_t)(row + 8) * N + col]);
                v0.x += r0.x; v0.y += r0.y; v1.x += r1.x; v1.y += r1.y;
            }
            *reinterpret_cast<float2*>(&C[(size_t)row * N + col]) = v0;
            *reinterpret_cast<float2*>(&C[(size_t)(row + 8) * N + col]) = v1;
        }
    }
}

// ===========================================================================
// QKV split + RoPE -> q hi/lo fp16 split, k single fp16, [bh][t][d]
// ===========================================================================
__global__ __launch_bounds__(512) void rope_kernel(
    const float* __restrict__ qkv,
    __half* __restrict__ qh, __half* __restrict__ ql,
    __half* __restrict__ k16)
{
    const int row = blockIdx.x;
    const int b = row >> 11;
    const int t = row & (TT - 1);
    const int tid = threadIdx.x;
    const int h = tid >> 5;
    const int i = tid & 31;

    const float* base = qkv + (size_t)row * (3 * CC) + h * HD;
    const float inv = powf(10000.0f, -(float)i * (1.0f / 32.0f));
    float s, c;
    sincosf((float)t * inv, &s, &c);

    const float qe = base[2*i],      qo = base[2*i + 1];
    const float ke = base[CC + 2*i], ko = base[CC + 2*i + 1];

    const size_t ob = ((size_t)((b * NH + h)) * TT + t) * HD;
    split_store_h(qe * c - qo * s, &qh[ob + 2*i],     &ql[ob + 2*i]);
    split_store_h(qe * s + qo * c, &qh[ob + 2*i + 1], &ql[ob + 2*i + 1]);
    k16[ob + 2*i]     = __float2half(ke * c - ko * s);
    k16[ob + 2*i + 1] = __float2half(ke * s + ko * c);
}

// ===========================================================================
// V transpose + fp16 split: qkv v-part [b,t,h*d] -> vth/vtl [bh][d][t]
// ===========================================================================
__global__ __launch_bounds__(256) void vtpose_kernel(
    const float* __restrict__ qkv,
    __half* __restrict__ vth, __half* __restrict__ vtl)
{
    __shared__ float tile[64][65];
    const int bh = blockIdx.y;
    const int b = bh / NH, h = bh % NH;
    const int t0 = blockIdx.x * 64;
    const int tid = threadIdx.x;
    for (int u = tid; u < 64*64; u += 256) {
        const int r = u >> 6, c = u & 63;
        tile[r][c] = qkv[((size_t)(b * TT + t0 + r)) * (3*CC) + 2*CC + h * HD + c];
    }
    __syncthreads();
    for (int u = tid; u < 64*64; u += 256) {
        const int d = u >> 6, c = u & 63;
        const float v = tile[c][d];
        const size_t idx = ((size_t)bh * HD + d) * TT + t0 + c;
        split_store_h(v, &vth[idx], &vtl[idx]);
    }
}

// ===========================================================================
// Tensor-core flash attention, fp16 2-combo, double-buffered K/V tiles.
// QK: (Qh+Ql)·K  PV: P·(Vh+Vl). fp32 softmax.
// SMEM: Qh,Ql tiles + 2 stages of {K, Vth, Vtl}.
// ===========================================================================
#define AT_S 144
#define AT_T (64*AT_S)           // 9216 B
#define AQ_BYTES (2*AT_T)        // 18432
#define AKV_STG (3*AT_T)         // 27648
#define ATT_SMEM (AQ_BYTES + 2*AKV_STG)   // 73728 B

__global__ __launch_bounds__(128, 2) void attn_kernel(
    const __half* __restrict__ Qh_, const __half* __restrict__ Ql_,
    const __half* __restrict__ K_,
    const __half* __restrict__ Vth_, const __half* __restrict__ Vtl_,
    const int* __restrict__ ymask,
    __half* __restrict__ Y)
{
    extern __shared__ char smatt[];
    __shared__ int ym[64];
    const uint32_t smb = smem_to_u32(smatt);
    const int tid = threadIdx.x, warp = tid >> 5, lane = tid & 31;
    const int bh = blockIdx.y, b = bh / NH, h = bh % NH;
    const int qt = (TT/64 - 1) - blockIdx.x;   // long rows first

    // group 0: Q tiles
    {
        const __half* q0 = Qh_ + ((size_t)bh * TT + qt * 64) * HD;
        const __half* q1 = Ql_ + ((size_t)bh * TT + qt * 64) * HD;
        for (int u = tid; u < 512; u += 128) {
            const int row = u >> 3, q8 = u & 7;
            CP_ASYNC16(smb + 0*AT_T + row*AT_S + q8*16, q0 + (size_t)row*HD + q8*8);
            CP_ASYNC16(smb + 1*AT_T + row*AT_S + q8*16, q1 + (size_t)row*HD + q8*8);
        }
        CP_COMMIT();
    }

    auto load_kv = [&](int kt, int stg) {
        const __half* s0 = K_   + ((size_t)bh * TT + kt * 64) * HD;
        const __half* s2 = Vth_ + (size_t)bh * HD * TT + kt * 64;
        const __half* s3 = Vtl_ + (size_t)bh * HD * TT + kt * 64;
        const uint32_t sb = smb + AQ_BYTES + stg * AKV_STG;
        for (int u = tid; u < 512; u += 128) {
            const int row = u >> 3, q8 = u & 7;
            CP_ASYNC16(sb + 0*AT_T + row*AT_S + q8*16, s0 + (size_t)row*HD + q8*8);
            CP_ASYNC16(sb + 1*AT_T + row*AT_S + q8*16, s2 + (size_t)row*TT + q8*8);
            CP_ASYNC16(sb + 2*AT_T + row*AT_S + q8*16, s3 + (size_t)row*TT + q8*8);
        }
        CP_COMMIT();
    };

    load_kv(0, 0);                 // group 1
    if (tid < 64) ym[tid] = ymask[b * 64 + tid];

    CP_WAIT(1);                    // Q tiles ready (kv0 may still fly)
    __syncthreads();

    // Q fragments (per warp: rows warp*16..+15)
    const uint32_t aoff = (uint32_t)(warp * 16 * AT_S + (lane & 15) * AT_S + (lane >> 4) * 16);
    uint32_t qfh[4][4], qfl[4][4];
    #pragma unroll
    for (int kc = 0; kc < 4; ++kc) {
        ldsm_x4(qfh[kc][0], qfh[kc][1], qfh[kc][2], qfh[kc][3], smb + 0*AT_T + kc*32 + aoff);
        ldsm_x4(qfl[kc][0], qfl[kc][1], qfl[kc][2], qfl[kc][3], smb + 1*AT_T + kc*32 + aoff);
    }

    const uint32_t boff = (uint32_t)(((lane & 7) + ((lane >> 4) << 3)) * AT_S
                                     + (((lane >> 3) & 1) << 4));

    float o[8][4];
    #pragma unroll
    for (int i = 0; i < 8; ++i)
        #pragma unroll
        for (int j = 0; j < 4; ++j) o[i][j] = 0.f;
    float mA = -1e30f, mB = -1e30f, lA = 0.f, lB = 0.f;

    const int rA = warp * 16 + (lane >> 2);
    const int rB = rA + 8;
    const int qgA = qt * 64 + rA, qgB = qt * 64 + rB;
    const int colb = (lane & 3) * 2;

    for (int kt = 0; kt <= qt; ++kt) {
        if (kt + 1 <= qt) {
            load_kv(kt + 1, (kt + 1) & 1);
            CP_WAIT(1);            // stage kt ready; kt+1 in flight
        } else {
            CP_WAIT(0);
        }
        __syncthreads();

        const uint32_t kvb = smb + AQ_BYTES + (kt & 1) * AKV_STG;

        // ---- S = Q K^T (2-combo) ----
        float s[8][4];
        #pragma unroll
        for (int i = 0; i < 8; ++i)
            #pragma unroll
            for (int j = 0; j < 4; ++j) s[i][j] = 0.f;
        #pragma unroll
        for (int kc = 0; kc < 4; ++kc) {
            uint32_t kb[8][2];
            #pragma unroll
            for (int pr = 0; pr < 4; ++pr) {
                uint32_t r0, r1, r2, r3;
                ldsm_x4(r0, r1, r2, r3, kvb + (uint32_t)(pr*16)*AT_S + kc*32 + boff);
                kb[2*pr][0]=r0; kb[2*pr][1]=r1; kb[2*pr+1][0]=r2; kb[2*pr+1][1]=r3;
            }
            #pragma unroll
            for (int nt = 0; nt < 8; ++nt) mma_fp16(s[nt], qfh[kc], kb[nt]);
            #pragma unroll
            for (int nt = 0; nt < 8; ++nt) mma_fp16(s[nt], qfl[kc], kb[nt]);
        }

        // ---- scale + mask ----
        const bool diag = (kt == qt);
        #pragma unroll
        for (int nt = 0; nt < 8; ++nt) {
            s[nt][0] *= 0.125f; s[nt][1] *= 0.125f;
            s[nt][2] *= 0.125f; s[nt][3] *= 0.125f;
        }
        if (diag) {
            const int ymA = (qt == 0) ? ym[rA] : 0;
            const int ymB = (qt == 0) ? ym[rB] : 0;
            #pragma unroll
            for (int nt = 0; nt < 8; ++nt) {
                const int c0 = nt * 8 + colb;
                const int kg0 = kt * 64 + c0, kg1 = kg0 + 1;
                bool a0 = kg0 <= qgA, a1 = kg1 <= qgA;
                bool b0 = kg0 <= qgB, b1 = kg1 <= qgB;
                if (qt == 0) {
                    const int k0 = ym[c0], k1 = ym[c0 + 1];
                    a0 = a0 || (ymA && k0); a1 = a1 || (ymA && k1);
                    b0 = b0 || (ymB && k0); b1 = b1 || (ymB && k1);
                }
                if (!a0) s[nt][0] = -1e30f;
                if (!a1) s[nt][1] = -1e30f;
                if (!b0) s[nt][2] = -1e30f;
                if (!b1) s[nt][3] = -1e30f;
            }
        }

        // ---- online softmax (rows A and B) ----
        float mxA = s[0][0], mxB = s[0][2];
        #pragma unroll
        for (int nt = 0; nt < 8; ++nt) {
            mxA = fmaxf(mxA, fmaxf(s[nt][0], s[nt][1]));
            mxB = fmaxf(mxB, fmaxf(s[nt][2], s[nt][3]));
        }
        mxA = fmaxf(mxA, __shfl_xor_sync(0xffffffffu, mxA, 1));
        mxA = fmaxf(mxA, __shfl_xor_sync(0xffffffffu, mxA, 2));
        mxB = fmaxf(mxB, __shfl_xor_sync(0xffffffffu, mxB, 1));
        mxB = fmaxf(mxB, __shfl_xor_sync(0xffffffffu, mxB, 2));
        const float mnA = fmaxf(mA, mxA), mnB = fmaxf(mB, mxB);
        const float cA = __expf(mA - mnA), cB = __expf(mB - mnB);
        mA = mnA; mB = mnB;
        float psA = 0.f, psB = 0.f;
        #pragma unroll
        for (int nt = 0; nt < 8; ++nt) {
            s[nt][0] = __expf(s[nt][0] - mnA); psA += s[nt][0];
            s[nt][1] = __expf(s[nt][1] - mnA); psA += s[nt][1];
            s[nt][2] = __expf(s[nt][2] - mnB); psB += s[nt][2];
            s[nt][3] = __expf(s[nt][3] - mnB); psB += s[nt][3];
        }
        lA = lA * cA + psA;
        lB = lB * cB + psB;
        #pragma unroll
        for (int nt = 0; nt < 8; ++nt) {
            o[nt][0] *= cA; o[nt][1] *= cA;
            o[nt][2] *= cB; o[nt][3] *= cB;
        }

        // ---- pack P (single fp16) ----
        uint32_t pf[4][4];
        #pragma unroll
        for (int kc = 0; kc < 4; ++kc) {
            pf[kc][0] = pack_h2(s[2*kc][0],   s[2*kc][1]);
            pf[kc][1] = pack_h2(s[2*kc][2],   s[2*kc][3]);
            pf[kc][2] = pack_h2(s[2*kc+1][0], s[2*kc+1][1]);
            pf[kc][3] = pack_h2(s[2*kc+1][2], s[2*kc+1][3]);
        }

        // ---- O += P (Vh + Vl) (2-combo) ----
        #pragma unroll
        for (int kc = 0; kc < 4; ++kc) {
            uint32_t vbh[8][2], vbl[8][2];
            #pragma unroll
            for (int pr = 0; pr < 4; ++pr) {
                uint32_t r0, r1, r2, r3;
                ldsm_x4(r0, r1, r2, r3, kvb + 1*AT_T + (uint32_t)(pr*16)*AT_S + kc*32 + boff);
                vbh[2*pr][0]=r0; vbh[2*pr][1]=r1; vbh[2*pr+1][0]=r2; vbh[2*pr+1][1]=r3;
                ldsm_x4(r0, r1, r2, r3, kvb + 2*AT_T + (uint32_t)(pr*16)*AT_S + kc*32 + boff);
                vbl[2*pr][0]=r0; vbl[2*pr][1]=r1; vbl[2*pr+1][0]=r2; vbl[2*pr+1][1]=r3;
            }
            #pragma unroll
            for (int nt = 0; nt < 8; ++nt) mma_fp16(o[nt], pf[kc], vbh[nt]);
            #pragma unroll
            for (int nt = 0; nt < 8; ++nt) mma_fp16(o[nt], pf[kc], vbl[nt]);
        }
        __syncthreads();   // all reads of stage (kt&1) done before next overwrite
    }

    lA += __shfl_xor_sync(0xffffffffu, lA, 1);
    lA += __shfl_xor_sync(0xffffffffu, lA, 2);
    lB += __shfl_xor_sync(0xffffffffu, lB, 1);
    lB += __shfl_xor_sync(0xffffffffu, lB, 2);
    const float iA = 1.0f / lA, iB = 1.0f / lB;
    const size_t baseA = ((size_t)(b * TT + qgA)) * CC + h * HD;
    const size_t baseB = ((size_t)(b * TT + qgB)) * CC + h * HD;
    #pragma unroll
    for (int nt = 0; nt < 8; ++nt) {
        const int col = nt * 8 + colb;
        __half2 a2 = __floats2half2_rn(o[nt][0] * iA, o[nt][1] * iA);
        __half2 b2 = __floats2half2_rn(o[nt][2] * iB, o[nt][3] * iB);
        *reinterpret_cast<__half2*>(&Y[baseA + col]) = a2;
        *reinterpret_cast<__half2*>(&Y[baseB + col]) = b2;
    }
}

// ===========================================================================
// silu(a)*b -> single fp16 output
// ===========================================================================
__global__ __launch_bounds__(256) void silu_h_kernel(
    const float* __restrict__ A, const float* __restrict__ B,
    __half* __restrict__ O, int n4)
{
    const int i = blockIdx.x * blockDim.x + threadIdx.x;
    if (i >= n4) return;
    float4 a = reinterpret_cast<const float4*>(A)[i];
    float4 b = reinterpret_cast<const float4*>(B)[i];
    float m0 = a.x / (1.f + __expf(-a.x)) * b.x;
    float m1 = a.y / (1.f + __expf(-a.y)) * b.y;
    float m2 = a.z / (1.f + __expf(-a.z)) * b.z;
    float m3 = a.w / (1.f + __expf(-a.w)) * b.w;
    __half2 o01 = __floats2half2_rn(m0, m1);
    __half2 o23 = __floats2half2_rn(m2, m3);
    uint2 pack;
    pack.x = *reinterpret_cast<uint32_t*>(&o01);
    pack.y = *reinterpret_cast<uint32_t*>(&o23);
    reinterpret_cast<uint2*>(O)[i] = pack;
}

// ===========================================================================
// launch
// ===========================================================================
extern "C" void kernel_launch(void* const* d_in, const int* in_sizes, int n_in,
                              void* d_out, int out_size)
{
    const float* x          = (const float*)d_in[0];
    const int*   y_mask     = (const int*)  d_in[1];
    const float* Wqkv       = (const float*)d_in[2];
    const float* Wattn_proj = (const float*)d_in[3];
    const float* scale1     = (const float*)d_in[4];
    const float* scale2     = (const float*)d_in[5];
    const float* Wfc1       = (const float*)d_in[6];
    const float* Wfc2       = (const float*)d_in[7];
    const float* Wmlp_proj  = (const float*)d_in[8];
    float* out = (float*)d_out;

    static bool attr_done = false;
    if (!attr_done) {
        cudaFuncSetAttribute(gemm_kernel, cudaFuncAttributeMaxDynamicSharedMemorySize, GSM_TOTAL);
        cudaFuncSetAttribute(attn_kernel, cudaFuncAttributeMaxDynamicSharedMemorySize, ATT_SMEM);
        attr_done = true;
    }

    __half *h16, *y16, *a16, *qh, *ql, *k16, *vth, *vtl;
    __half *wqh, *wql, *wah, *wal, *w1h, *w1l, *w2h, *w2l, *wmh, *wml;
    float *qkv, *x1, *fc1, *fc2;
    cudaGetSymbolAddress((void**)&h16, g_h16);
    cudaGetSymbolAddress((void**)&qkv, g_qkv);
    cudaGetSymbolAddress((void**)&qh, g_qh);   cudaGetSymbolAddress((void**)&ql, g_ql);
    cudaGetSymbolAddress((void**)&k16, g_k16);
    cudaGetSymbolAddress((void**)&vth, g_vth); cudaGetSymbolAddress((void**)&vtl, g_vtl);
    cudaGetSymbolAddress((void**)&y16, g_y16);
    cudaGetSymbolAddress((void**)&x1, g_x1);
    cudaGetSymbolAddress((void**)&fc1, g_fc1); cudaGetSymbolAddress((void**)&fc2, g_fc2);
    cudaGetSymbolAddress((void**)&a16, g_a16);
    cudaGetSymbolAddress((void**)&wqh, g_wqkv_h); cudaGetSymbolAddress((void**)&wql, g_wqkv_l);
    cudaGetSymbolAddress((void**)&wah, g_watt_h); cudaGetSymbolAddress((void**)&wal, g_watt_l);
    cudaGetSymbolAddress((void**)&w1h, g_wf1_h);  cudaGetSymbolAddress((void**)&w1l, g_wf1_l);
    cudaGetSymbolAddress((void**)&w2h, g_wf2_h);  cudaGetSymbolAddress((void**)&w2l, g_wf2_l);
    cudaGetSymbolAddress((void**)&wmh, g_wmlp_h); cudaGetSymbolAddress((void**)&wml, g_wmlp_l);

    // merged weight transpose + split (one launch)
    {
        TpAll p;
        p.W[0] = Wqkv;       p.Th[0] = wqh; p.Tl[0] = wql; p.K[0] = CC;  p.N[0] = 3*CC;
        p.W[1] = Wattn_proj; p.Th[1] = wah; p.Tl[1] = wal; p.K[1] = CC;  p.N[1] = CC;
        p.W[2] = Wfc1;       p.Th[2] = w1h; p.Tl[2] = w1l; p.K[2] = CC;  p.N[2] = HID;
        p.W[3] = Wfc2;       p.Th[3] = w2h; p.Tl[3] = w2l; p.K[3] = CC;  p.N[3] = HID;
        p.W[4] = Wmlp_proj;  p.Th[4] = wmh; p.Tl[4] = wml; p.K[4] = HID; p.N[4] = CC;
        int acc = 0;
        for (int i = 0; i < 5; ++i) {
            p.start[i] = acc;
            acc += (p.N[i] >> 5) * (p.K[i] >> 5);
        }
        p.start[5] = acc;
        tpose_all_kernel<<<acc, 256>>>(p);
    }

    // 1. h = rmsnorm(x, scale1) -> fp16
    rmsnorm_h_kernel<<<BT, 256>>>(x, scale1, h16);

    // 2. qkv = h @ Wqkv
    gemm_kernel<<<dim3(3*CC/128, BT/128), 256, GSM_TOTAL>>>(
        BT, 3*CC, CC, h16, wqh, wql, nullptr, qkv);

    // 3. rope (q split, k single) + v transpose (fp16 split)
    rope_kernel<<<BT, 512>>>(qkv, qh, ql, k16);
    vtpose_kernel<<<dim3(TT/64, BB*NH), 256>>>(qkv, vth, vtl);

    // 4. tensor-core flash attention (fp16 2-combo, pipelined) -> fp16 y
    attn_kernel<<<dim3(TT/64, BB*NH), 128, ATT_SMEM>>>(
        qh, ql, k16, vth, vtl, y_mask, y16);

    // 5. x1 = x + y @ Wattn_proj
    gemm_kernel<<<dim3(CC/128, BT/128), 256, GSM_TOTAL>>>(
        BT, CC, CC, y16, wah, wal, x, x1);

    // 6. h = rmsnorm(x1, scale2) -> fp16
    rmsnorm_h_kernel<<<BT, 256>>>(x1, scale2, h16);

    // 7. fc1, fc2
    gemm_kernel<<<dim3(HID/128, BT/128), 256, GSM_TOTAL>>>(
        BT, HID, CC, h16, w1h, w1l, nullptr, fc1);
    gemm_kernel<<<dim3(HID/128, BT/128), 256, GSM_TOTAL>>>(
        BT, HID, CC, h16, w2h, w2l, nullptr, fc2);

    // 8. a = silu(fc1)*fc2 -> fp16
    silu_h_kernel<<<(BT*HID/4 + 255)/256, 256>>>(fc1, fc2, a16, BT*HID/4);

    // 9. out = x1 + a @ Wmlp_proj
    gemm_kernel<<<dim3(CC/128, BT/128), 256, GSM_TOTAL>>>(
        BT, CC, HID, a16, wmh, wml, x1, out);
}

// round 16
// speedup vs baseline: 1.5325x; 1.5325x over previous
#include <cuda_runtime.h>
#include <cuda_bf16.h>
#include <cuda_fp16.h>
#include <math.h>
#include <stdint.h>

// Problem constants
#define BB 2
#define TT 2048
#define CC 1024
#define NH 16
#define HD 64
#define HID 2816
#define BT (BB*TT)          // 4096 rows

// ===========================================================================
// Scratch (static device globals; no allocations anywhere)
// ===========================================================================
__device__ __align__(16) __half g_h16[BT*CC];        // rmsnorm out (fp16)
__device__ __align__(16) float  g_qkv[BT*3*CC];
__device__ __align__(16) __half g_qh [BB*NH*TT*HD];  // roped q hi (fp16)
__device__ __align__(16) __half g_ql [BB*NH*TT*HD];  // roped q lo
__device__ __align__(16) __half g_k16[BB*NH*TT*HD];  // roped k (single fp16)
__device__ __align__(16) __half g_vth[BB*NH*HD*TT];  // [bh][d][t] hi
__device__ __align__(16) __half g_vtl[BB*NH*HD*TT];  // [bh][d][t] lo
__device__ __align__(16) __half g_y16[BT*CC];        // attn out (fp16)
__device__ __align__(16) float  g_x1 [BT*CC];
__device__ __align__(16) float  g_fc1[BT*HID];
__device__ __align__(16) float  g_fc2[BT*HID];
__device__ __align__(16) __half g_a16[BT*HID];       // silu out (fp16)
// transposed + split weights, [N,K] K-major fp16 hi/lo
__device__ __align__(16) __half g_wqkv_h[3*CC*CC];
__device__ __align__(16) __half g_wqkv_l[3*CC*CC];
__device__ __align__(16) __half g_watt_h[CC*CC];
__device__ __align__(16) __half g_watt_l[CC*CC];
__device__ __align__(16) __half g_wf1_h[HID*CC];
__device__ __align__(16) __half g_wf1_l[HID*CC];
__device__ __align__(16) __half g_wf2_h[HID*CC];
__device__ __align__(16) __half g_wf2_l[HID*CC];
__device__ __align__(16) __half g_wmlp_h[CC*HID];
__device__ __align__(16) __half g_wmlp_l[CC*HID];

__device__ __forceinline__ void split_store_h(float v, __half* ph, __half* pl) {
    __half hi = __float2half(v);
    *ph = hi;
    *pl = __float2half(v - __half2float(hi));
}

__device__ __forceinline__ uint32_t smem_to_u32(const void* p) {
    uint32_t a;
    asm("{ .reg .u64 t; cvta.to.shared.u64 t, %1; cvt.u32.u64 %0, t; }" : "=r"(a) : "l"(p));
    return a;
}

// ===========================================================================
// mma.sync / ldmatrix / cp.async helpers (all valid on compute_103)
// ===========================================================================
__device__ __forceinline__ void ldsm_x4(uint32_t& r0, uint32_t& r1, uint32_t& r2,
                                        uint32_t& r3, uint32_t addr) {
    asm volatile("ldmatrix.sync.aligned.m8n8.x4.shared.b16 {%0,%1,%2,%3}, [%4];"
                 : "=r"(r0), "=r"(r1), "=r"(r2), "=r"(r3) : "r"(addr));
}
__device__ __forceinline__ void mma_fp16(float* d, const uint32_t* a, const uint32_t* b) {
    asm volatile(
        "mma.sync.aligned.m16n8k16.row.col.f32.f16.f16.f32 "
        "{%0,%1,%2,%3}, {%4,%5,%6,%7}, {%8,%9}, {%0,%1,%2,%3};"
        : "+f"(d[0]), "+f"(d[1]), "+f"(d[2]), "+f"(d[3])
        : "r"(a[0]), "r"(a[1]), "r"(a[2]), "r"(a[3]), "r"(b[0]), "r"(b[1]));
}
#define CP_ASYNC16(dst, src) \
    asm volatile("cp.async.cg.shared.global [%0], [%1], 16;" :: "r"(dst), "l"(src))
#define CP_COMMIT() asm volatile("cp.async.commit_group;" ::: "memory")
#define CP_WAIT(n)  asm volatile("cp.async.wait_group %0;" :: "n"(n) : "memory")

__device__ __forceinline__ uint32_t pack_h2(float f0, float f1) {
    __half2 h = __floats2half2_rn(f0, f1);
    return *reinterpret_cast<uint32_t*>(&h);
}

// ===========================================================================
// Merged weight transpose + fp16 split: all 5 weights in one launch.
// ===========================================================================
struct TpAll {
    const float* W[5];
    __half* Th[5];
    __half* Tl[5];
    int K[5];
    int N[5];
    int start[6];
};

__global__ __launch_bounds__(256) void tpose_all_kernel(TpAll p)
{
    __shared__ float tile[32][33];
    int bid = blockIdx.x;
    int w = 0;
    #pragma unroll
    for (int i = 0; i < 4; ++i) if (bid >= p.start[i + 1]) w = i + 1;
    const int local = bid - p.start[w];
    const int K = p.K[w], N = p.N[w];
    const int ntn = N >> 5;
    const int n0 = (local % ntn) * 32, k0 = (local / ntn) * 32;
    const float* W = p.W[w];
    __half* Th = p.Th[w];
    __half* Tl = p.Tl[w];

    const int tx = threadIdx.x & 31, ty = threadIdx.x >> 5;
    #pragma unroll
    for (int i = 0; i < 4; ++i) {
        int k = ty + i * 8;
        tile[k][tx] = W[(size_t)(k0 + k) * N + n0 + tx];
    }
    __syncthreads();
    #pragma unroll
    for (int i = 0; i < 4; ++i) {
        int n = ty + i * 8;
        float v = tile[tx][n];
        size_t idx = (size_t)(n0 + n) * K + k0 + tx;
        split_store_h(v, &Th[idx], &Tl[idx]);
    }
}

// ===========================================================================
// RMSNorm -> single fp16 output
// ===========================================================================
__global__ __launch_bounds__(256) void rmsnorm_h_kernel(
    const float* __restrict__ x, const float* __restrict__ scale,
    __half* __restrict__ oh)
{
    const int row = blockIdx.x;
    const int t   = threadIdx.x;
    float4 v = reinterpret_cast<const float4*>(x + (size_t)row * CC)[t];
    float ss = v.x*v.x + v.y*v.y + v.z*v.z + v.w*v.w;
    __shared__ float red[8];
    #pragma unroll
    for (int o = 16; o > 0; o >>= 1) ss += __shfl_down_sync(0xffffffffu, ss, o);
    if ((t & 31) == 0) red[t >> 5] = ss;
    __syncthreads();
    if (t < 32) {
        float s2 = (t < 8) ? red[t] : 0.f;
        #pragma unroll
        for (int o = 4; o > 0; o >>= 1) s2 += __shfl_down_sync(0xffffffffu, s2, o);
        if (t == 0) red[0] = s2;
    }
    __syncthreads();
    const float rs = rsqrtf(red[0] * (1.0f / CC) + 1e-5f);
    const float4 s4 = reinterpret_cast<const float4*>(scale)[t];
    __half2 o01 = __floats2half2_rn(v.x * rs * s4.x, v.y * rs * s4.y);
    __half2 o23 = __floats2half2_rn(v.z * rs * s4.z, v.w * rs * s4.w);
    uint2 pack;
    pack.x = *reinterpret_cast<uint32_t*>(&o01);
    pack.y = *reinterpret_cast<uint32_t*>(&o23);
    reinterpret_cast<uint2*>(oh + (size_t)row * CC)[t] = pack;
}

// ===========================================================================
// HMMA GEMM (fp16, 2-combo): C[M,N] = A[M,K] @ (Bh+Bl)[N,K]^T (+ R)
// CTA 128x128, BK=32, 8 warps (2x4), warp tile 64x32, m16n8k16 f16.
// ===========================================================================
#define TROW 80                       // padded row stride (bytes)
#define TILE_B (128*TROW)             // 10240 B per matrix tile
#define STAGE_B (3*TILE_B)            // A,Bh,Bl = 30720 B
#define GSM_TOTAL (2*STAGE_B)         // 61440 B

__global__ __launch_bounds__(256) void gemm_kernel(
    int M, int N, int K,
    const __half* __restrict__ A,
    const __half* __restrict__ Bh, const __half* __restrict__ Bl,
    const float* __restrict__ R, float* __restrict__ C)
{
    extern __shared__ char sm[];
    const uint32_t smb = smem_to_u32(sm);
    const int tid = threadIdx.x;
    const int wid = tid >> 5, lane = tid & 31;
    const int warp_m = wid >> 2;          // 0..1
    const int warp_n = wid & 3;           // 0..3
    const int m0 = blockIdx.y * 128, n0 = blockIdx.x * 128;

    const __half* srcs[3] = {
        A + (size_t)m0 * K, Bh + (size_t)n0 * K, Bl + (size_t)n0 * K };

    const int NC = K >> 5;   // chunks of 32

    auto load_stage = [&](int stage, int kc) {
        const uint32_t sb = smb + stage * STAGE_B;
        #pragma unroll
        for (int mtx = 0; mtx < 3; ++mtx) {
            const __half* s = srcs[mtx] + kc;
            const uint32_t tb = sb + mtx * TILE_B;
            #pragma unroll
            for (int u = tid; u < 512; u += 256) {
                const int row = u >> 2, q = u & 3;
                CP_ASYNC16(tb + row * TROW + q * 16, s + (size_t)row * K + q * 8);
            }
        }
        CP_COMMIT();
    };

    load_stage(0, 0);
    if (NC > 1) load_stage(1, 32);

    float acc[4][4][4] = {};

    const uint32_t aoff = (uint32_t)((lane & 15) * TROW + (lane >> 4) * 16);
    const uint32_t boff = (uint32_t)(((lane & 7) + ((lane >> 4) << 3)) * TROW
                                     + (((lane >> 3) & 1) << 4));

    for (int c = 0; c < NC; ++c) {
        if (c + 1 < NC) { CP_WAIT(1); } else { CP_WAIT(0); }
        __syncthreads();

        const uint32_t sb = smb + (c & 1) * STAGE_B;
        const uint32_t baseA  = sb              + (uint32_t)(warp_m * 64) * TROW;
        const uint32_t baseBh = sb + TILE_B     + (uint32_t)(warp_n * 32) * TROW;
        const uint32_t baseBl = sb + 2 * TILE_B + (uint32_t)(warp_n * 32) * TROW;

        #pragma unroll
        for (int kk = 0; kk < 2; ++kk) {
            const uint32_t kb = kk * 32;
            uint32_t bh[4][2], bl[4][2];
            #pragma unroll
            for (int pr = 0; pr < 2; ++pr) {
                uint32_t r0, r1, r2, r3;
                ldsm_x4(r0, r1, r2, r3, baseBh + (uint32_t)(pr * 16) * TROW + kb + boff);
                bh[2*pr][0] = r0; bh[2*pr][1] = r1; bh[2*pr+1][0] = r2; bh[2*pr+1][1] = r3;
                ldsm_x4(r0, r1, r2, r3, baseBl + (uint32_t)(pr * 16) * TROW + kb + boff);
                bl[2*pr][0] = r0; bl[2*pr][1] = r1; bl[2*pr+1][0] = r2; bl[2*pr+1][1] = r3;
            }
            uint32_t af[4][4];
            #pragma unroll
            for (int mt = 0; mt < 4; ++mt)
                ldsm_x4(af[mt][0], af[mt][1], af[mt][2], af[mt][3],
                        baseA + (uint32_t)(mt * 16) * TROW + kb + aoff);
            #pragma unroll
            for (int mt = 0; mt < 4; ++mt)
                #pragma unroll
                for (int nt = 0; nt < 4; ++nt)
                    mma_fp16(acc[mt][nt], af[mt], bh[nt]);
            #pragma unroll
            for (int mt = 0; mt < 4; ++mt)
                #pragma unroll
                for (int nt = 0; nt < 4; ++nt)
                    mma_fp16(acc[mt][nt], af[mt], bl[nt]);
        }
        __syncthreads();
        if (c + 2 < NC) load_stage(c & 1, (c + 2) << 5);
    }

    const int rl = lane >> 2, cl = (lane & 3) * 2;
    #pragma unroll
    for (int mt = 0; mt < 4; ++mt) {
        #pragma unroll
        for (int nt = 0; nt < 4; ++nt) {
            const int row = m0 + warp_m * 64 + mt * 16 + rl;
            const int col = n0 + warp_n * 32 + nt * 8 + cl;
            float2 v0 = make_float2(acc[mt][nt][0], acc[mt][nt][1]);
            float2 v1 = make_float2(acc[mt][nt][2], acc[mt][nt][3]);
            if (R) {
                float2 r0 = *reinterpret_cast<const float2*>(&R[(size_t)row * N + col]);
                float2 r1 = *reinterpret_cast<const float2*>(&R[(size_t)(row + 8) * N + col]);
                v0.x += r0.x; v0.y += r0.y; v1.x += r1.x; v1.y += r1.y;
            }
            *reinterpret_cast<float2*>(&C[(size_t)row * N + col]) = v0;
            *reinterpret_cast<float2*>(&C[(size_t)(row + 8) * N + col]) = v1;
        }
    }
}

// ===========================================================================
// QKV split + RoPE -> q hi/lo fp16 split, k single fp16, [bh][t][d]
// ===========================================================================
__global__ __launch_bounds__(512) void rope_kernel(
    const float* __restrict__ qkv,
    __half* __restrict__ qh, __half* __restrict__ ql,
    __half* __restrict__ k16)
{
    const int row = blockIdx.x;
    const int b = row >> 11;
    const int t = row & (TT - 1);
    const int tid = threadIdx.x;
    const int h = tid >> 5;
    const int i = tid & 31;

    const float* base = qkv + (size_t)row * (3 * CC) + h * HD;
    const float inv = powf(10000.0f, -(float)i * (1.0f / 32.0f));
    float s, c;
    sincosf((float)t * inv, &s, &c);

    const float qe = base[2*i],      qo = base[2*i + 1];
    const float ke = base[CC + 2*i], ko = base[CC + 2*i + 1];

    const size_t ob = ((size_t)((b * NH + h)) * TT + t) * HD;
    split_store_h(qe * c - qo * s, &qh[ob + 2*i],     &ql[ob + 2*i]);
    split_store_h(qe * s + qo * c, &qh[ob + 2*i + 1], &ql[ob + 2*i + 1]);
    k16[ob + 2*i]     = __float2half(ke * c - ko * s);
    k16[ob + 2*i + 1] = __float2half(ke * s + ko * c);
}

// ===========================================================================
// V transpose + fp16 split: qkv v-part [b,t,h*d] -> vth/vtl [bh][d][t]
// ===========================================================================
__global__ __launch_bounds__(256) void vtpose_kernel(
    const float* __restrict__ qkv,
    __half* __restrict__ vth, __half* __restrict__ vtl)
{
    __shared__ float tile[64][65];
    const int bh = blockIdx.y;
    const int b = bh / NH, h = bh % NH;
    const int t0 = blockIdx.x * 64;
    const int tid = threadIdx.x;
    for (int u = tid; u < 64*64; u += 256) {
        const int r = u >> 6, c = u & 63;
        tile[r][c] = qkv[((size_t)(b * TT + t0 + r)) * (3*CC) + 2*CC + h * HD + c];
    }
    __syncthreads();
    for (int u = tid; u < 64*64; u += 256) {
        const int d = u >> 6, c = u & 63;
        const float v = tile[c][d];
        const size_t idx = ((size_t)bh * HD + d) * TT + t0 + c;
        split_store_h(v, &vth[idx], &vtl[idx]);
    }
}

// ===========================================================================
// Tensor-core flash attention, fp16 2-combo, R13 serial-load structure.
// QK: (Qh+Ql)·K   PV: P·(Vh+Vl). fp32 softmax.
// SMEM: Qh,Ql + single stage {K, Vth, Vtl} = 5 tiles.
// ===========================================================================
#define AT_S 144
#define AT_T (64*AT_S)           // 9216 B
#define ATT_SMEM (5*AT_T)        // 46080 B

__global__ __launch_bounds__(128, 2) void attn_kernel(
    const __half* __restrict__ Qh_, const __half* __restrict__ Ql_,
    const __half* __restrict__ K_,
    const __half* __restrict__ Vth_, const __half* __restrict__ Vtl_,
    const int* __restrict__ ymask,
    __half* __restrict__ Y)
{
    extern __shared__ char smatt[];
    __shared__ int ym[64];
    const uint32_t smb = smem_to_u32(smatt);
    const int tid = threadIdx.x, warp = tid >> 5, lane = tid & 31;
    const int bh = blockIdx.y, b = bh / NH, h = bh % NH;
    const int qt = (TT/64 - 1) - blockIdx.x;   // long rows first

    // Q tiles (hi, lo)
    {
        const __half* q0 = Qh_ + ((size_t)bh * TT + qt * 64) * HD;
        const __half* q1 = Ql_ + ((size_t)bh * TT + qt * 64) * HD;
        for (int u = tid; u < 512; u += 128) {
            const int row = u >> 3, q8 = u & 7;
            CP_ASYNC16(smb + 0*AT_T + row*AT_S + q8*16, q0 + (size_t)row*HD + q8*8);
            CP_ASYNC16(smb + 1*AT_T + row*AT_S + q8*16, q1 + (size_t)row*HD + q8*8);
        }
        CP_COMMIT();
    }
    if (tid < 64) ym[tid] = ymask[b * 64 + tid];
    CP_WAIT(0);
    __syncthreads();

    // Q fragments (per warp: rows warp*16..+15)
    const uint32_t aoff = (uint32_t)(warp * 16 * AT_S + (lane & 15) * AT_S + (lane >> 4) * 16);
    uint32_t qfh[4][4], qfl[4][4];
    #pragma unroll
    for (int kc = 0; kc < 4; ++kc) {
        ldsm_x4(qfh[kc][0], qfh[kc][1], qfh[kc][2], qfh[kc][3], smb + 0*AT_T + kc*32 + aoff);
        ldsm_x4(qfl[kc][0], qfl[kc][1], qfl[kc][2], qfl[kc][3], smb + 1*AT_T + kc*32 + aoff);
    }

    const uint32_t boff = (uint32_t)(((lane & 7) + ((lane >> 4) << 3)) * AT_S
                                     + (((lane >> 3) & 1) << 4));

    float o[8][4];
    #pragma unroll
    for (int i = 0; i < 8; ++i)
        #pragma unroll
        for (int j = 0; j < 4; ++j) o[i][j] = 0.f;
    float mA = -1e30f, mB = -1e30f, lA = 0.f, lB = 0.f;

    const int rA = warp * 16 + (lane >> 2);
    const int rB = rA + 8;
    const int qgA = qt * 64 + rA, qgB = qt * 64 + rB;
    const int colb = (lane & 3) * 2;

    for (int kt = 0; kt <= qt; ++kt) {
        __syncthreads();
        {
            const __half* s0 = K_   + ((size_t)bh * TT + kt * 64) * HD;
            const __half* s2 = Vth_ + (size_t)bh * HD * TT + kt * 64;
            const __half* s3 = Vtl_ + (size_t)bh * HD * TT + kt * 64;
            for (int u = tid; u < 512; u += 128) {
                const int row = u >> 3, q8 = u & 7;
                CP_ASYNC16(smb + 2*AT_T + row*AT_S + q8*16, s0 + (size_t)row*HD + q8*8);
                CP_ASYNC16(smb + 3*AT_T + row*AT_S + q8*16, s2 + (size_t)row*TT + q8*8);
                CP_ASYNC16(smb + 4*AT_T + row*AT_S + q8*16, s3 + (size_t)row*TT + q8*8);
            }
            CP_COMMIT(); CP_WAIT(0);
        }
        __syncthreads();

        // ---- S = Q K^T (2-combo) ----
        float s[8][4];
        #pragma unroll
        for (int i = 0; i < 8; ++i)
            #pragma unroll
            for (int j = 0; j < 4; ++j) s[i][j] = 0.f;
        #pragma unroll
        for (int kc = 0; kc < 4; ++kc) {
            uint32_t kb[8][2];
            #pragma unroll
            for (int pr = 0; pr < 4; ++pr) {
                uint32_t r0, r1, r2, r3;
                ldsm_x4(r0, r1, r2, r3, smb + 2*AT_T + (uint32_t)(pr*16)*AT_S + kc*32 + boff);
                kb[2*pr][0]=r0; kb[2*pr][1]=r1; kb[2*pr+1][0]=r2; kb[2*pr+1][1]=r3;
            }
            #pragma unroll
            for (int nt = 0; nt < 8; ++nt) mma_fp16(s[nt], qfh[kc], kb[nt]);
            #pragma unroll
            for (int nt = 0; nt < 8; ++nt) mma_fp16(s[nt], qfl[kc], kb[nt]);
        }

        // ---- scale + mask ----
        const bool diag = (kt == qt);
        #pragma unroll
        for (int nt = 0; nt < 8; ++nt) {
            s[nt][0] *= 0.125f; s[nt][1] *= 0.125f;
            s[nt][2] *= 0.125f; s[nt][3] *= 0.125f;
        }
        if (diag) {
            const int ymA = (qt == 0) ? ym[rA] : 0;
            const int ymB = (qt == 0) ? ym[rB] : 0;
            #pragma unroll
            for (int nt = 0; nt < 8; ++nt) {
                const int c0 = nt * 8 + colb;
                const int kg0 = kt * 64 + c0, kg1 = kg0 + 1;
                bool a0 = kg0 <= qgA, a1 = kg1 <= qgA;
                bool b0 = kg0 <= qgB, b1 = kg1 <= qgB;
                if (qt == 0) {
                    const int k0 = ym[c0], k1 = ym[c0 + 1];
                    a0 = a0 || (ymA && k0); a1 = a1 || (ymA && k1);
                    b0 = b0 || (ymB && k0); b1 = b1 || (ymB && k1);
                }
                if (!a0) s[nt][0] = -1e30f;
                if (!a1) s[nt][1] = -1e30f;
                if (!b0) s[nt][2] = -1e30f;
                if (!b1) s[nt][3] = -1e30f;
            }
        }

        // ---- online softmax (rows A and B) ----
        float mxA = s[0][0], mxB = s[0][2];
        #pragma unroll
        for (int nt = 0; nt < 8; ++nt) {
            mxA = fmaxf(mxA, fmaxf(s[nt][0], s[nt][1]));
            mxB = fmaxf(mxB, fmaxf(s[nt][2], s[nt][3]));
        }
        mxA = fmaxf(mxA, __shfl_xor_sync(0xffffffffu, mxA, 1));
        mxA = fmaxf(mxA, __shfl_xor_sync(0xffffffffu, mxA, 2));
        mxB = fmaxf(mxB, __shfl_xor_sync(0xffffffffu, mxB, 1));
        mxB = fmaxf(mxB, __shfl_xor_sync(0xffffffffu, mxB, 2));
        const float mnA = fmaxf(mA, mxA), mnB = fmaxf(mB, mxB);
        const float cA = __expf(mA - mnA), cB = __expf(mB - mnB);
        mA = mnA; mB = mnB;
        float psA = 0.f, psB = 0.f;
        #pragma unroll
        for (int nt = 0; nt < 8; ++nt) {
            s[nt][0] = __expf(s[nt][0] - mnA); psA += s[nt][0];
            s[nt][1] = __expf(s[nt][1] - mnA); psA += s[nt][1];
            s[nt][2] = __expf(s[nt][2] - mnB); psB += s[nt][2];
            s[nt][3] = __expf(s[nt][3] - mnB); psB += s[nt][3];
        }
        lA = lA * cA + psA;
        lB = lB * cB + psB;
        #pragma unroll
        for (int nt = 0; nt < 8; ++nt) {
            o[nt][0] *= cA; o[nt][1] *= cA;
            o[nt][2] *= cB; o[nt][3] *= cB;
        }

        // ---- pack P (single fp16) ----
        uint32_t pf[4][4];
        #pragma unroll
        for (int kc = 0; kc < 4; ++kc) {
            pf[kc][0] = pack_h2(s[2*kc][0],   s[2*kc][1]);
            pf[kc][1] = pack_h2(s[2*kc][2],   s[2*kc][3]);
            pf[kc][2] = pack_h2(s[2*kc+1][0], s[2*kc+1][1]);
            pf[kc][3] = pack_h2(s[2*kc+1][2], s[2*kc+1][3]);
        }

        // ---- O += P (Vh + Vl) (2-combo) ----
        #pragma unroll
        for (int kc = 0; kc < 4; ++kc) {
            uint32_t vbh[8][2], vbl[8][2];
            #pragma unroll
            for (int pr = 0; pr < 4; ++pr) {
                uint32_t r0, r1, r2, r3;
                ldsm_x4(r0, r1, r2, r3, smb + 3*AT_T + (uint32_t)(pr*16)*AT_S + kc*32 + boff);
                vbh[2*pr][0]=r0; vbh[2*pr][1]=r1; vbh[2*pr+1][0]=r2; vbh[2*pr+1][1]=r3;
                ldsm_x4(r0, r1, r2, r3, smb + 4*AT_T + (uint32_t)(pr*16)*AT_S + kc*32 + boff);
                vbl[2*pr][0]=r0; vbl[2*pr][1]=r1; vbl[2*pr+1][0]=r2; vbl[2*pr+1][1]=r3;
            }
            #pragma unroll
            for (int nt = 0; nt < 8; ++nt) mma_fp16(o[nt], pf[kc], vbh[nt]);
            #pragma unroll
            for (int nt = 0; nt < 8; ++nt) mma_fp16(o[nt], pf[kc], vbl[nt]);
        }
    }

    lA += __shfl_xor_sync(0xffffffffu, lA, 1);
    lA += __shfl_xor_sync(0xffffffffu, lA, 2);
    lB += __shfl_xor_sync(0xffffffffu, lB, 1);
    lB += __shfl_xor_sync(0xffffffffu, lB, 2);
    const float iA = 1.0f / lA, iB = 1.0f / lB;
    const size_t baseA = ((size_t)(b * TT + qgA)) * CC + h * HD;
    const size_t baseB = ((size_t)(b * TT + qgB)) * CC + h * HD;
    #pragma unroll
    for (int nt = 0; nt < 8; ++nt) {
        const int col = nt * 8 + colb;
        __half2 a2 = __floats2half2_rn(o[nt][0] * iA, o[nt][1] * iA);
        __half2 b2 = __floats2half2_rn(o[nt][2] * iB, o[nt][3] * iB);
        *reinterpret_cast<__half2*>(&Y[baseA + col]) = a2;
        *reinterpret_cast<__half2*>(&Y[baseB + col]) = b2;
    }
}

// ===========================================================================
// silu(a)*b -> single fp16 output
// ===========================================================================
__global__ __launch_bounds__(256) void silu_h_kernel(
    const float* __restrict__ A, const float* __restrict__ B,
    __half* __restrict__ O, int n4)
{
    const int i = blockIdx.x * blockDim.x + threadIdx.x;
    if (i >= n4) return;
    float4 a = reinterpret_cast<const float4*>(A)[i];
    float4 b = reinterpret_cast<const float4*>(B)[i];
    float m0 = a.x / (1.f + __expf(-a.x)) * b.x;
    float m1 = a.y / (1.f + __expf(-a.y)) * b.y;
    float m2 = a.z / (1.f + __expf(-a.z)) * b.z;
    float m3 = a.w / (1.f + __expf(-a.w)) * b.w;
    __half2 o01 = __floats2half2_rn(m0, m1);
    __half2 o23 = __floats2half2_rn(m2, m3);
    uint2 pack;
    pack.x = *reinterpret_cast<uint32_t*>(&o01);
    pack.y = *reinterpret_cast<uint32_t*>(&o23);
    reinterpret_cast<uint2*>(O)[i] = pack;
}

// ===========================================================================
// launch
// ===========================================================================
extern "C" void kernel_launch(void* const* d_in, const int* in_sizes, int n_in,
                              void* d_out, int out_size)
{
    const float* x          = (const float*)d_in[0];
    const int*   y_mask     = (const int*)  d_in[1];
    const float* Wqkv       = (const float*)d_in[2];
    const float* Wattn_proj = (const float*)d_in[3];
    const float* scale1     = (const float*)d_in[4];
    const float* scale2     = (const float*)d_in[5];
    const float* Wfc1       = (const float*)d_in[6];
    const float* Wfc2       = (const float*)d_in[7];
    const float* Wmlp_proj  = (const float*)d_in[8];
    float* out = (float*)d_out;

    static bool attr_done = false;
    if (!attr_done) {
        cudaFuncSetAttribute(gemm_kernel, cudaFuncAttributeMaxDynamicSharedMemorySize, GSM_TOTAL);
        cudaFuncSetAttribute(attn_kernel, cudaFuncAttributeMaxDynamicSharedMemorySize, ATT_SMEM);
        attr_done = true;
    }

    __half *h16, *y16, *a16, *qh, *ql, *k16, *vth, *vtl;
    __half *wqh, *wql, *wah, *wal, *w1h, *w1l, *w2h, *w2l, *wmh, *wml;
    float *qkv, *x1, *fc1, *fc2;
    cudaGetSymbolAddress((void**)&h16, g_h16);
    cudaGetSymbolAddress((void**)&qkv, g_qkv);
    cudaGetSymbolAddress((void**)&qh, g_qh);   cudaGetSymbolAddress((void**)&ql, g_ql);
    cudaGetSymbolAddress((void**)&k16, g_k16);
    cudaGetSymbolAddress((void**)&vth, g_vth); cudaGetSymbolAddress((void**)&vtl, g_vtl);
    cudaGetSymbolAddress((void**)&y16, g_y16);
    cudaGetSymbolAddress((void**)&x1, g_x1);
    cudaGetSymbolAddress((void**)&fc1, g_fc1); cudaGetSymbolAddress((void**)&fc2, g_fc2);
    cudaGetSymbolAddress((void**)&a16, g_a16);
    cudaGetSymbolAddress((void**)&wqh, g_wqkv_h); cudaGetSymbolAddress((void**)&wql, g_wqkv_l);
    cudaGetSymbolAddress((void**)&wah, g_watt_h); cudaGetSymbolAddress((void**)&wal, g_watt_l);
    cudaGetSymbolAddress((void**)&w1h, g_wf1_h);  cudaGetSymbolAddress((void**)&w1l, g_wf1_l);
    cudaGetSymbolAddress((void**)&w2h, g_wf2_h);  cudaGetSymbolAddress((void**)&w2l, g_wf2_l);
    cudaGetSymbolAddress((void**)&wmh, g_wmlp_h); cudaGetSymbolAddress((void**)&wml, g_wmlp_l);

    // merged weight transpose + split (one launch)
    {
        TpAll p;
        p.W[0] = Wqkv;       p.Th[0] = wqh; p.Tl[0] = wql; p.K[0] = CC;  p.N[0] = 3*CC;
        p.W[1] = Wattn_proj; p.Th[1] = wah; p.Tl[1] = wal; p.K[1] = CC;  p.N[1] = CC;
        p.W[2] = Wfc1;       p.Th[2] = w1h; p.Tl[2] = w1l; p.K[2] = CC;  p.N[2] = HID;
        p.W[3] = Wfc2;       p.Th[3] = w2h; p.Tl[3] = w2l; p.K[3] = CC;  p.N[3] = HID;
        p.W[4] = Wmlp_proj;  p.Th[4] = wmh; p.Tl[4] = wml; p.K[4] = HID; p.N[4] = CC;
        int acc = 0;
        for (int i = 0; i < 5; ++i) {
            p.start[i] = acc;
            acc += (p.N[i] >> 5) * (p.K[i] >> 5);
        }
        p.start[5] = acc;
        tpose_all_kernel<<<acc, 256>>>(p);
    }

    // 1. h = rmsnorm(x, scale1) -> fp16
    rmsnorm_h_kernel<<<BT, 256>>>(x, scale1, h16);

    // 2. qkv = h @ Wqkv
    gemm_kernel<<<dim3(3*CC/128, BT/128), 256, GSM_TOTAL>>>(
        BT, 3*CC, CC, h16, wqh, wql, nullptr, qkv);

    // 3. rope (q split, k single) + v transpose (fp16 split)
    rope_kernel<<<BT, 512>>>(qkv, qh, ql, k16);
    vtpose_kernel<<<dim3(TT/64, BB*NH), 256>>>(qkv, vth, vtl);

    // 4. tensor-core flash attention (fp16 2-combo, serial loads) -> fp16 y
    attn_kernel<<<dim3(TT/64, BB*NH), 128, ATT_SMEM>>>(
        qh, ql, k16, vth, vtl, y_mask, y16);

    // 5. x1 = x + y @ Wattn_proj
    gemm_kernel<<<dim3(CC/128, BT/128), 256, GSM_TOTAL>>>(
        BT, CC, CC, y16, wah, wal, x, x1);

    // 6. h = rmsnorm(x1, scale2) -> fp16
    rmsnorm_h_kernel<<<BT, 256>>>(x1, scale2, h16);

    // 7. fc1, fc2
    gemm_kernel<<<dim3(HID/128, BT/128), 256, GSM_TOTAL>>>(
        BT, HID, CC, h16, w1h, w1l, nullptr, fc1);
    gemm_kernel<<<dim3(HID/128, BT/128), 256, GSM_TOTAL>>>(
        BT, HID, CC, h16, w2h, w2l, nullptr, fc2);

    // 8. a = silu(fc1)*fc2 -> fp16
    silu_h_kernel<<<(BT*HID/4 + 255)/256, 256>>>(fc1, fc2, a16, BT*HID/4);

    // 9. out = x1 + a @ Wmlp_proj
    gemm_kernel<<<dim3(CC/128, BT/128), 256, GSM_TOTAL>>>(
        BT, CC, HID, a16, wmh, wml, x1, out);
}

// round 17
// speedup vs baseline: 2.0615x; 1.3452x over previous
#include <cuda_runtime.h>
#include <cuda_bf16.h>
#include <cuda_fp16.h>
#include <math.h>
#include <stdint.h>

// Problem constants
#define BB 2
#define TT 2048
#define CC 1024
#define NH 16
#define HD 64
#define HID 2816
#define BT (BB*TT)          // 4096 rows

// ===========================================================================
// Scratch (static device globals; no allocations anywhere)
// ===========================================================================
__device__ __align__(16) __half g_h16[BT*CC];        // rmsnorm out (fp16)
__device__ __align__(16) float  g_qkv[BT*3*CC];
__device__ __align__(16) __half g_qh [BB*NH*TT*HD];  // roped q hi (fp16)
__device__ __align__(16) __half g_ql [BB*NH*TT*HD];  // roped q lo
__device__ __align__(16) __half g_k16[BB*NH*TT*HD];  // roped k (single fp16)
__device__ __align__(16) __half g_vth[BB*NH*HD*TT];  // [bh][d][t] hi
__device__ __align__(16) __half g_vtl[BB*NH*HD*TT];  // [bh][d][t] lo
__device__ __align__(16) __half g_y16[BT*CC];        // attn out (fp16)
__device__ __align__(16) float  g_x1 [BT*CC];
__device__ __align__(16) float  g_fc1[BT*HID];
__device__ __align__(16) float  g_fc2[BT*HID];
__device__ __align__(16) __half g_a16[BT*HID];       // silu out (fp16)
// transposed weights, [N,K] K-major single fp16
__device__ __align__(16) __half g_wqkv[3*CC*CC];
__device__ __align__(16) __half g_watt[CC*CC];
__device__ __align__(16) __half g_wf1 [HID*CC];
__device__ __align__(16) __half g_wf2 [HID*CC];
__device__ __align__(16) __half g_wmlp[CC*HID];

__device__ __forceinline__ void split_store_h(float v, __half* ph, __half* pl) {
    __half hi = __float2half(v);
    *ph = hi;
    *pl = __float2half(v - __half2float(hi));
}

__device__ __forceinline__ uint32_t smem_to_u32(const void* p) {
    uint32_t a;
    asm("{ .reg .u64 t; cvta.to.shared.u64 t, %1; cvt.u32.u64 %0, t; }" : "=r"(a) : "l"(p));
    return a;
}

// ===========================================================================
// mma.sync / ldmatrix / cp.async helpers (all valid on compute_103)
// ===========================================================================
__device__ __forceinline__ void ldsm_x4(uint32_t& r0, uint32_t& r1, uint32_t& r2,
                                        uint32_t& r3, uint32_t addr) {
    asm volatile("ldmatrix.sync.aligned.m8n8.x4.shared.b16 {%0,%1,%2,%3}, [%4];"
                 : "=r"(r0), "=r"(r1), "=r"(r2), "=r"(r3) : "r"(addr));
}
__device__ __forceinline__ void mma_fp16(float* d, const uint32_t* a, const uint32_t* b) {
    asm volatile(
        "mma.sync.aligned.m16n8k16.row.col.f32.f16.f16.f32 "
        "{%0,%1,%2,%3}, {%4,%5,%6,%7}, {%8,%9}, {%0,%1,%2,%3};"
        : "+f"(d[0]), "+f"(d[1]), "+f"(d[2]), "+f"(d[3])
        : "r"(a[0]), "r"(a[1]), "r"(a[2]), "r"(a[3]), "r"(b[0]), "r"(b[1]));
}
#define CP_ASYNC16(dst, src) \
    asm volatile("cp.async.cg.shared.global [%0], [%1], 16;" :: "r"(dst), "l"(src))
#define CP_COMMIT() asm volatile("cp.async.commit_group;" ::: "memory")
#define CP_WAIT(n)  asm volatile("cp.async.wait_group %0;" :: "n"(n) : "memory")

__device__ __forceinline__ uint32_t pack_h2(float f0, float f1) {
    __half2 h = __floats2half2_rn(f0, f1);
    return *reinterpret_cast<uint32_t*>(&h);
}

// ===========================================================================
// Merged weight transpose -> single fp16: all 5 weights in one launch.
// ===========================================================================
struct TpAll {
    const float* W[5];
    __half* T[5];
    int K[5];
    int N[5];
    int start[6];
};

__global__ __launch_bounds__(256) void tpose_all_kernel(TpAll p)
{
    __shared__ float tile[32][33];
    int bid = blockIdx.x;
    int w = 0;
    #pragma unroll
    for (int i = 0; i < 4; ++i) if (bid >= p.start[i + 1]) w = i + 1;
    const int local = bid - p.start[w];
    const int K = p.K[w], N = p.N[w];
    const int ntn = N >> 5;
    const int n0 = (local % ntn) * 32, k0 = (local / ntn) * 32;
    const float* W = p.W[w];
    __half* T = p.T[w];

    const int tx = threadIdx.x & 31, ty = threadIdx.x >> 5;
    #pragma unroll
    for (int i = 0; i < 4; ++i) {
        int k = ty + i * 8;
        tile[k][tx] = W[(size_t)(k0 + k) * N + n0 + tx];
    }
    __syncthreads();
    #pragma unroll
    for (int i = 0; i < 4; ++i) {
        int n = ty + i * 8;
        T[(size_t)(n0 + n) * K + k0 + tx] = __float2half(tile[tx][n]);
    }
}

// ===========================================================================
// RMSNorm -> single fp16 output
// ===========================================================================
__global__ __launch_bounds__(256) void rmsnorm_h_kernel(
    const float* __restrict__ x, const float* __restrict__ scale,
    __half* __restrict__ oh)
{
    const int row = blockIdx.x;
    const int t   = threadIdx.x;
    float4 v = reinterpret_cast<const float4*>(x + (size_t)row * CC)[t];
    float ss = v.x*v.x + v.y*v.y + v.z*v.z + v.w*v.w;
    __shared__ float red[8];
    #pragma unroll
    for (int o = 16; o > 0; o >>= 1) ss += __shfl_down_sync(0xffffffffu, ss, o);
    if ((t & 31) == 0) red[t >> 5] = ss;
    __syncthreads();
    if (t < 32) {
        float s2 = (t < 8) ? red[t] : 0.f;
        #pragma unroll
        for (int o = 4; o > 0; o >>= 1) s2 += __shfl_down_sync(0xffffffffu, s2, o);
        if (t == 0) red[0] = s2;
    }
    __syncthreads();
    const float rs = rsqrtf(red[0] * (1.0f / CC) + 1e-5f);
    const float4 s4 = reinterpret_cast<const float4*>(scale)[t];
    __half2 o01 = __floats2half2_rn(v.x * rs * s4.x, v.y * rs * s4.y);
    __half2 o23 = __floats2half2_rn(v.z * rs * s4.z, v.w * rs * s4.w);
    uint2 pack;
    pack.x = *reinterpret_cast<uint32_t*>(&o01);
    pack.y = *reinterpret_cast<uint32_t*>(&o23);
    reinterpret_cast<uint2*>(oh + (size_t)row * CC)[t] = pack;
}

// ===========================================================================
// HMMA GEMM (pure fp16, 1-combo): C[M,N] = A[M,K] @ B[N,K]^T (+ R)
// CTA 128x128, BK=32, 8 warps (2x4), warp tile 64x32, m16n8k16 f16.
// ===========================================================================
#define TROW 80                       // padded row stride (bytes)
#define TILE_B (128*TROW)             // 10240 B per matrix tile
#define STAGE_B (2*TILE_B)            // A,B = 20480 B
#define GSM_TOTAL (2*STAGE_B)         // 40960 B

__global__ __launch_bounds__(256) void gemm_kernel(
    int M, int N, int K,
    const __half* __restrict__ A, const __half* __restrict__ B,
    const float* __restrict__ R, float* __restrict__ C)
{
    extern __shared__ char sm[];
    const uint32_t smb = smem_to_u32(sm);
    const int tid = threadIdx.x;
    const int wid = tid >> 5, lane = tid & 31;
    const int warp_m = wid >> 2;          // 0..1
    const int warp_n = wid & 3;           // 0..3
    const int m0 = blockIdx.y * 128, n0 = blockIdx.x * 128;

    const __half* srcs[2] = { A + (size_t)m0 * K, B + (size_t)n0 * K };

    const int NC = K >> 5;   // chunks of 32

    auto load_stage = [&](int stage, int kc) {
        const uint32_t sb = smb + stage * STAGE_B;
        #pragma unroll
        for (int mtx = 0; mtx < 2; ++mtx) {
            const __half* s = srcs[mtx] + kc;
            const uint32_t tb = sb + mtx * TILE_B;
            #pragma unroll
            for (int u = tid; u < 512; u += 256) {
                const int row = u >> 2, q = u & 3;
                CP_ASYNC16(tb + row * TROW + q * 16, s + (size_t)row * K + q * 8);
            }
        }
        CP_COMMIT();
    };

    load_stage(0, 0);
    if (NC > 1) load_stage(1, 32);

    float acc[4][4][4] = {};

    const uint32_t aoff = (uint32_t)((lane & 15) * TROW + (lane >> 4) * 16);
    const uint32_t boff = (uint32_t)(((lane & 7) + ((lane >> 4) << 3)) * TROW
                                     + (((lane >> 3) & 1) << 4));

    for (int c = 0; c < NC; ++c) {
        if (c + 1 < NC) { CP_WAIT(1); } else { CP_WAIT(0); }
        __syncthreads();

        const uint32_t sb = smb + (c & 1) * STAGE_B;
        const uint32_t baseA = sb          + (uint32_t)(warp_m * 64) * TROW;
        const uint32_t baseB = sb + TILE_B + (uint32_t)(warp_n * 32) * TROW;

        #pragma unroll
        for (int kk = 0; kk < 2; ++kk) {
            const uint32_t kb = kk * 32;
            uint32_t bf[4][2];
            #pragma unroll
            for (int pr = 0; pr < 2; ++pr) {
                uint32_t r0, r1, r2, r3;
                ldsm_x4(r0, r1, r2, r3, baseB + (uint32_t)(pr * 16) * TROW + kb + boff);
                bf[2*pr][0] = r0; bf[2*pr][1] = r1; bf[2*pr+1][0] = r2; bf[2*pr+1][1] = r3;
            }
            uint32_t af[4][4];
            #pragma unroll
            for (int mt = 0; mt < 4; ++mt)
                ldsm_x4(af[mt][0], af[mt][1], af[mt][2], af[mt][3],
                        baseA + (uint32_t)(mt * 16) * TROW + kb + aoff);
            #pragma unroll
            for (int mt = 0; mt < 4; ++mt)
                #pragma unroll
                for (int nt = 0; nt < 4; ++nt)
                    mma_fp16(acc[mt][nt], af[mt], bf[nt]);
        }
        __syncthreads();
        if (c + 2 < NC) load_stage(c & 1, (c + 2) << 5);
    }

    const int rl = lane >> 2, cl = (lane & 3) * 2;
    #pragma unroll
    for (int mt = 0; mt < 4; ++mt) {
        #pragma unroll
        for (int nt = 0; nt < 4; ++nt) {
            const int row = m0 + warp_m * 64 + mt * 16 + rl;
            const int col = n0 + warp_n * 32 + nt * 8 + cl;
            float2 v0 = make_float2(acc[mt][nt][0], acc[mt][nt][1]);
            float2 v1 = make_float2(acc[mt][nt][2], acc[mt][nt][3]);
            if (R) {
                float2 r0 = *reinterpret_cast<const float2*>(&R[(size_t)row * N + col]);
                float2 r1 = *reinterpret_cast<const float2*>(&R[(size_t)(row + 8) * N + col]);
                v0.x += r0.x; v0.y += r0.y; v1.x += r1.x; v1.y += r1.y;
            }
            *reinterpret_cast<float2*>(&C[(size_t)row * N + col]) = v0;
            *reinterpret_cast<float2*>(&C[(size_t)(row + 8) * N + col]) = v1;
        }
    }
}

// ===========================================================================
// QKV split + RoPE -> q hi/lo fp16 split, k single fp16, [bh][t][d]
// ===========================================================================
__global__ __launch_bounds__(512) void rope_kernel(
    const float* __restrict__ qkv,
    __half* __restrict__ qh, __half* __restrict__ ql,
    __half* __restrict__ k16)
{
    const int row = blockIdx.x;
    const int b = row >> 11;
    const int t = row & (TT - 1);
    const int tid = threadIdx.x;
    const int h = tid >> 5;
    const int i = tid & 31;

    const float* base = qkv + (size_t)row * (3 * CC) + h * HD;
    const float inv = powf(10000.0f, -(float)i * (1.0f / 32.0f));
    float s, c;
    sincosf((float)t * inv, &s, &c);

    const float qe = base[2*i],      qo = base[2*i + 1];
    const float ke = base[CC + 2*i], ko = base[CC + 2*i + 1];

    const size_t ob = ((size_t)((b * NH + h)) * TT + t) * HD;
    split_store_h(qe * c - qo * s, &qh[ob + 2*i],     &ql[ob + 2*i]);
    split_store_h(qe * s + qo * c, &qh[ob + 2*i + 1], &ql[ob + 2*i + 1]);
    k16[ob + 2*i]     = __float2half(ke * c - ko * s);
    k16[ob + 2*i + 1] = __float2half(ke * s + ko * c);
}

// ===========================================================================
// V transpose + fp16 split: qkv v-part [b,t,h*d] -> vth/vtl [bh][d][t]
// ===========================================================================
__global__ __launch_bounds__(256) void vtpose_kernel(
    const float* __restrict__ qkv,
    __half* __restrict__ vth, __half* __restrict__ vtl)
{
    __shared__ float tile[64][65];
    const int bh = blockIdx.y;
    const int b = bh / NH, h = bh % NH;
    const int t0 = blockIdx.x * 64;
    const int tid = threadIdx.x;
    for (int u = tid; u < 64*64; u += 256) {
        const int r = u >> 6, c = u & 63;
        tile[r][c] = qkv[((size_t)(b * TT + t0 + r)) * (3*CC) + 2*CC + h * HD + c];
    }
    __syncthreads();
    for (int u = tid; u < 64*64; u += 256) {
        const int d = u >> 6, c = u & 63;
        const float v = tile[c][d];
        const size_t idx = ((size_t)bh * HD + d) * TT + t0 + c;
        split_store_h(v, &vth[idx], &vtl[idx]);
    }
}

// ===========================================================================
// Tensor-core flash attention, fp16 2-combo, serial-load structure.
// QK: (Qh+Ql)·K   PV: P·(Vh+Vl). fp32 softmax.
// SMEM: Qh,Ql + single stage {K, Vth, Vtl} = 5 tiles.
// ===========================================================================
#define AT_S 144
#define AT_T (64*AT_S)           // 9216 B
#define ATT_SMEM (5*AT_T)        // 46080 B

__global__ __launch_bounds__(128, 2) void attn_kernel(
    const __half* __restrict__ Qh_, const __half* __restrict__ Ql_,
    const __half* __restrict__ K_,
    const __half* __restrict__ Vth_, const __half* __restrict__ Vtl_,
    const int* __restrict__ ymask,
    __half* __restrict__ Y)
{
    extern __shared__ char smatt[];
    __shared__ int ym[64];
    const uint32_t smb = smem_to_u32(smatt);
    const int tid = threadIdx.x, warp = tid >> 5, lane = tid & 31;
    const int bh = blockIdx.y, b = bh / NH, h = bh % NH;
    const int qt = (TT/64 - 1) - blockIdx.x;   // long rows first

    // Q tiles (hi, lo)
    {
        const __half* q0 = Qh_ + ((size_t)bh * TT + qt * 64) * HD;
        const __half* q1 = Ql_ + ((size_t)bh * TT + qt * 64) * HD;
        for (int u = tid; u < 512; u += 128) {
            const int row = u >> 3, q8 = u & 7;
            CP_ASYNC16(smb + 0*AT_T + row*AT_S + q8*16, q0 + (size_t)row*HD + q8*8);
            CP_ASYNC16(smb + 1*AT_T + row*AT_S + q8*16, q1 + (size_t)row*HD + q8*8);
        }
        CP_COMMIT();
    }
    if (tid < 64) ym[tid] = ymask[b * 64 + tid];
    CP_WAIT(0);
    __syncthreads();

    // Q fragments (per warp: rows warp*16..+15)
    const uint32_t aoff = (uint32_t)(warp * 16 * AT_S + (lane & 15) * AT_S + (lane >> 4) * 16);
    uint32_t qfh[4][4], qfl[4][4];
    #pragma unroll
    for (int kc = 0; kc < 4; ++kc) {
        ldsm_x4(qfh[kc][0], qfh[kc][1], qfh[kc][2], qfh[kc][3], smb + 0*AT_T + kc*32 + aoff);
        ldsm_x4(qfl[kc][0], qfl[kc][1], qfl[kc][2], qfl[kc][3], smb + 1*AT_T + kc*32 + aoff);
    }

    const uint32_t boff = (uint32_t)(((lane & 7) + ((lane >> 4) << 3)) * AT_S
                                     + (((lane >> 3) & 1) << 4));

    float o[8][4];
    #pragma unroll
    for (int i = 0; i < 8; ++i)
        #pragma unroll
        for (int j = 0; j < 4; ++j) o[i][j] = 0.f;
    float mA = -1e30f, mB = -1e30f, lA = 0.f, lB = 0.f;

    const int rA = warp * 16 + (lane >> 2);
    const int rB = rA + 8;
    const int qgA = qt * 64 + rA, qgB = qt * 64 + rB;
    const int colb = (lane & 3) * 2;

    for (int kt = 0; kt <= qt; ++kt) {
        __syncthreads();
        {
            const __half* s0 = K_   + ((size_t)bh * TT + kt * 64) * HD;
            const __half* s2 = Vth_ + (size_t)bh * HD * TT + kt * 64;
            const __half* s3 = Vtl_ + (size_t)bh * HD * TT + kt * 64;
            for (int u = tid; u < 512; u += 128) {
                const int row = u >> 3, q8 = u & 7;
                CP_ASYNC16(smb + 2*AT_T + row*AT_S + q8*16, s0 + (size_t)row*HD + q8*8);
                CP_ASYNC16(smb + 3*AT_T + row*AT_S + q8*16, s2 + (size_t)row*TT + q8*8);
                CP_ASYNC16(smb + 4*AT_T + row*AT_S + q8*16, s3 + (size_t)row*TT + q8*8);
            }
            CP_COMMIT(); CP_WAIT(0);
        }
        __syncthreads();

        // ---- S = Q K^T (2-combo) ----
        float s[8][4];
        #pragma unroll
        for (int i = 0; i < 8; ++i)
            #pragma unroll
            for (int j = 0; j < 4; ++j) s[i][j] = 0.f;
        #pragma unroll
        for (int kc = 0; kc < 4; ++kc) {
            uint32_t kb[8][2];
            #pragma unroll
            for (int pr = 0; pr < 4; ++pr) {
                uint32_t r0, r1, r2, r3;
                ldsm_x4(r0, r1, r2, r3, smb + 2*AT_T + (uint32_t)(pr*16)*AT_S + kc*32 + boff);
                kb[2*pr][0]=r0; kb[2*pr][1]=r1; kb[2*pr+1][0]=r2; kb[2*pr+1][1]=r3;
            }
            #pragma unroll
            for (int nt = 0; nt < 8; ++nt) mma_fp16(s[nt], qfh[kc], kb[nt]);
            #pragma unroll
            for (int nt = 0; nt < 8; ++nt) mma_fp16(s[nt], qfl[kc], kb[nt]);
        }

        // ---- scale + mask ----
        const bool diag = (kt == qt);
        #pragma unroll
        for (int nt = 0; nt < 8; ++nt) {
            s[nt][0] *= 0.125f; s[nt][1] *= 0.125f;
            s[nt][2] *= 0.125f; s[nt][3] *= 0.125f;
        }
        if (diag) {
            const int ymA = (qt == 0) ? ym[rA] : 0;
            const int ymB = (qt == 0) ? ym[rB] : 0;
            #pragma unroll
            for (int nt = 0; nt < 8; ++nt) {
                const int c0 = nt * 8 + colb;
                const int kg0 = kt * 64 + c0, kg1 = kg0 + 1;
                bool a0 = kg0 <= qgA, a1 = kg1 <= qgA;
                bool b0 = kg0 <= qgB, b1 = kg1 <= qgB;
                if (qt == 0) {
                    const int k0 = ym[c0], k1 = ym[c0 + 1];
                    a0 = a0 || (ymA && k0); a1 = a1 || (ymA && k1);
                    b0 = b0 || (ymB && k0); b1 = b1 || (ymB && k1);
                }
                if (!a0) s[nt][0] = -1e30f;
                if (!a1) s[nt][1] = -1e30f;
                if (!b0) s[nt][2] = -1e30f;
                if (!b1) s[nt][3] = -1e30f;
            }
        }

        // ---- online softmax (rows A and B) ----
        float mxA = s[0][0], mxB = s[0][2];
        #pragma unroll
        for (int nt = 0; nt < 8; ++nt) {
            mxA = fmaxf(mxA, fmaxf(s[nt][0], s[nt][1]));
            mxB = fmaxf(mxB, fmaxf(s[nt][2], s[nt][3]));
        }
        mxA = fmaxf(mxA, __shfl_xor_sync(0xffffffffu, mxA, 1));
        mxA = fmaxf(mxA, __shfl_xor_sync(0xffffffffu, mxA, 2));
        mxB = fmaxf(mxB, __shfl_xor_sync(0xffffffffu, mxB, 1));
        mxB = fmaxf(mxB, __shfl_xor_sync(0xffffffffu, mxB, 2));
        const float mnA = fmaxf(mA, mxA), mnB = fmaxf(mB, mxB);
        const float cA = __expf(mA - mnA), cB = __expf(mB - mnB);
        mA = mnA; mB = mnB;
        float psA = 0.f, psB = 0.f;
        #pragma unroll
        for (int nt = 0; nt < 8; ++nt) {
            s[nt][0] = __expf(s[nt][0] - mnA); psA += s[nt][0];
            s[nt][1] = __expf(s[nt][1] - mnA); psA += s[nt][1];
            s[nt][2] = __expf(s[nt][2] - mnB); psB += s[nt][2];
            s[nt][3] = __expf(s[nt][3] - mnB); psB += s[nt][3];
        }
        lA = lA * cA + psA;
        lB = lB * cB + psB;
        #pragma unroll
        for (int nt = 0; nt < 8; ++nt) {
            o[nt][0] *= cA; o[nt][1] *= cA;
            o[nt][2] *= cB; o[nt][3] *= cB;
        }

        // ---- pack P (single fp16) ----
        uint32_t pf[4][4];
        #pragma unroll
        for (int kc = 0; kc < 4; ++kc) {
            pf[kc][0] = pack_h2(s[2*kc][0],   s[2*kc][1]);
            pf[kc][1] = pack_h2(s[2*kc][2],   s[2*kc][3]);
            pf[kc][2] = pack_h2(s[2*kc+1][0], s[2*kc+1][1]);
            pf[kc][3] = pack_h2(s[2*kc+1][2], s[2*kc+1][3]);
        }

        // ---- O += P (Vh + Vl) (2-combo) ----
        #pragma unroll
        for (int kc = 0; kc < 4; ++kc) {
            uint32_t vbh[8][2], vbl[8][2];
            #pragma unroll
            for (int pr = 0; pr < 4; ++pr) {
                uint32_t r0, r1, r2, r3;
                ldsm_x4(r0, r1, r2, r3, smb + 3*AT_T + (uint32_t)(pr*16)*AT_S + kc*32 + boff);
                vbh[2*pr][0]=r0; vbh[2*pr][1]=r1; vbh[2*pr+1][0]=r2; vbh[2*pr+1][1]=r3;
                ldsm_x4(r0, r1, r2, r3, smb + 4*AT_T + (uint32_t)(pr*16)*AT_S + kc*32 + boff);
                vbl[2*pr][0]=r0; vbl[2*pr][1]=r1; vbl[2*pr+1][0]=r2; vbl[2*pr+1][1]=r3;
            }
            #pragma unroll
            for (int nt = 0; nt < 8; ++nt) mma_fp16(o[nt], pf[kc], vbh[nt]);
            #pragma unroll
            for (int nt = 0; nt < 8; ++nt) mma_fp16(o[nt], pf[kc], vbl[nt]);
        }
    }

    lA += __shfl_xor_sync(0xffffffffu, lA, 1);
    lA += __shfl_xor_sync(0xffffffffu, lA, 2);
    lB += __shfl_xor_sync(0xffffffffu, lB, 1);
    lB += __shfl_xor_sync(0xffffffffu, lB, 2);
    const float iA = 1.0f / lA, iB = 1.0f / lB;
    const size_t baseA = ((size_t)(b * TT + qgA)) * CC + h * HD;
    const size_t baseB = ((size_t)(b * TT + qgB)) * CC + h * HD;
    #pragma unroll
    for (int nt = 0; nt < 8; ++nt) {
        const int col = nt * 8 + colb;
        __half2 a2 = __floats2half2_rn(o[nt][0] * iA, o[nt][1] * iA);
        __half2 b2 = __floats2half2_rn(o[nt][2] * iB, o[nt][3] * iB);
        *reinterpret_cast<__half2*>(&Y[baseA + col]) = a2;
        *reinterpret_cast<__half2*>(&Y[baseB + col]) = b2;
    }
}

// ===========================================================================
// silu(a)*b -> single fp16 output
// ===========================================================================
__global__ __launch_bounds__(256) void silu_h_kernel(
    const float* __restrict__ A, const float* __restrict__ B,
    __half* __restrict__ O, int n4)
{
    const int i = blockIdx.x * blockDim.x + threadIdx.x;
    if (i >= n4) return;
    float4 a = reinterpret_cast<const float4*>(A)[i];
    float4 b = reinterpret_cast<const float4*>(B)[i];
    float m0 = a.x / (1.f + __expf(-a.x)) * b.x;
    float m1 = a.y / (1.f + __expf(-a.y)) * b.y;
    float m2 = a.z / (1.f + __expf(-a.z)) * b.z;
    float m3 = a.w / (1.f + __expf(-a.w)) * b.w;
    __half2 o01 = __floats2half2_rn(m0, m1);
    __half2 o23 = __floats2half2_rn(m2, m3);
    uint2 pack;
    pack.x = *reinterpret_cast<uint32_t*>(&o01);
    pack.y = *reinterpret_cast<uint32_t*>(&o23);
    reinterpret_cast<uint2*>(O)[i] = pack;
}

// ===========================================================================
// launch
// ===========================================================================
extern "C" void kernel_launch(void* const* d_in, const int* in_sizes, int n_in,
                              void* d_out, int out_size)
{
    const float* x          = (const float*)d_in[0];
    const int*   y_mask     = (const int*)  d_in[1];
    const float* Wqkv       = (const float*)d_in[2];
    const float* Wattn_proj = (const float*)d_in[3];
    const float* scale1     = (const float*)d_in[4];
    const float* scale2     = (const float*)d_in[5];
    const float* Wfc1       = (const float*)d_in[6];
    const float* Wfc2       = (const float*)d_in[7];
    const float* Wmlp_proj  = (const float*)d_in[8];
    float* out = (float*)d_out;

    static bool attr_done = false;
    if (!attr_done) {
        cudaFuncSetAttribute(gemm_kernel, cudaFuncAttributeMaxDynamicSharedMemorySize, GSM_TOTAL);
        cudaFuncSetAttribute(attn_kernel, cudaFuncAttributeMaxDynamicSharedMemorySize, ATT_SMEM);
        attr_done = true;
    }

    __half *h16, *y16, *a16, *qh, *ql, *k16, *vth, *vtl;
    __half *wq, *wa, *w1, *w2, *wm;
    float *qkv, *x1, *fc1, *fc2;
    cudaGetSymbolAddress((void**)&h16, g_h16);
    cudaGetSymbolAddress((void**)&qkv, g_qkv);
    cudaGetSymbolAddress((void**)&qh, g_qh);   cudaGetSymbolAddress((void**)&ql, g_ql);
    cudaGetSymbolAddress((void**)&k16, g_k16);
    cudaGetSymbolAddress((void**)&vth, g_vth); cudaGetSymbolAddress((void**)&vtl, g_vtl);
    cudaGetSymbolAddress((void**)&y16, g_y16);
    cudaGetSymbolAddress((void**)&x1, g_x1);
    cudaGetSymbolAddress((void**)&fc1, g_fc1); cudaGetSymbolAddress((void**)&fc2, g_fc2);
    cudaGetSymbolAddress((void**)&a16, g_a16);
    cudaGetSymbolAddress((void**)&wq, g_wqkv);
    cudaGetSymbolAddress((void**)&wa, g_watt);
    cudaGetSymbolAddress((void**)&w1, g_wf1);
    cudaGetSymbolAddress((void**)&w2, g_wf2);
    cudaGetSymbolAddress((void**)&wm, g_wmlp);

    // merged weight transpose (one launch)
    {
        TpAll p;
        p.W[0] = Wqkv;       p.T[0] = wq; p.K[0] = CC;  p.N[0] = 3*CC;
        p.W[1] = Wattn_proj; p.T[1] = wa; p.K[1] = CC;  p.N[1] = CC;
        p.W[2] = Wfc1;       p.T[2] = w1; p.K[2] = CC;  p.N[2] = HID;
        p.W[3] = Wfc2;       p.T[3] = w2; p.K[3] = CC;  p.N[3] = HID;
        p.W[4] = Wmlp_proj;  p.T[4] = wm; p.K[4] = HID; p.N[4] = CC;
        int acc = 0;
        for (int i = 0; i < 5; ++i) {
            p.start[i] = acc;
            acc += (p.N[i] >> 5) * (p.K[i] >> 5);
        }
        p.start[5] = acc;
        tpose_all_kernel<<<acc, 256>>>(p);
    }

    // 1. h = rmsnorm(x, scale1) -> fp16
    rmsnorm_h_kernel<<<BT, 256>>>(x, scale1, h16);

    // 2. qkv = h @ Wqkv
    gemm_kernel<<<dim3(3*CC/128, BT/128), 256, GSM_TOTAL>>>(
        BT, 3*CC, CC, h16, wq, nullptr, qkv);

    // 3. rope (q split, k single) + v transpose (fp16 split)
    rope_kernel<<<BT, 512>>>(qkv, qh, ql, k16);
    vtpose_kernel<<<dim3(TT/64, BB*NH), 256>>>(qkv, vth, vtl);

    // 4. tensor-core flash attention (fp16 2-combo) -> fp16 y
    attn_kernel<<<dim3(TT/64, BB*NH), 128, ATT_SMEM>>>(
        qh, ql, k16, vth, vtl, y_mask, y16);

    // 5. x1 = x + y @ Wattn_proj
    gemm_kernel<<<dim3(CC/128, BT/128), 256, GSM_TOTAL>>>(
        BT, CC, CC, y16, wa, x, x1);

    // 6. h = rmsnorm(x1, scale2) -> fp16
    rmsnorm_h_kernel<<<BT, 256>>>(x1, scale2, h16);

    // 7. fc1, fc2
    gemm_kernel<<<dim3(HID/128, BT/128), 256, GSM_TOTAL>>>(
        BT, HID, CC, h16, w1, nullptr, fc1);
    gemm_kernel<<<dim3(HID/128, BT/128), 256, GSM_TOTAL>>>(
        BT, HID, CC, h16, w2, nullptr, fc2);

    // 8. a = silu(fc1)*fc2 -> fp16
    silu_h_kernel<<<(BT*HID/4 + 255)/256, 256>>>(fc1, fc2, a16, BT*HID/4);

    // 9. out = x1 + a @ Wmlp_proj
    gemm_kernel<<<dim3(CC/128, BT/128), 256, GSM_TOTAL>>>(
        BT, CC, HID, a16, wm, x1, out);
}